// round 7
// baseline (speedup 1.0000x reference)
#include <cuda_runtime.h>
#include <cuda_bf16.h>
#include <cstdint>
#include <math.h>

#define H 16
#define DMODEL 1024
#define DK 64
#define NB 2
#define SEQ 2048
#define MROWS (NB*SEQ)   // 4096
#define BHN (NB*H)       // 32

// ---------------- scratch (device globals; no allocation allowed) ----------
__device__ __nv_bfloat16 s_qh[MROWS * DMODEL], s_ql[MROWS * DMODEL];
__device__ __nv_bfloat16 s_kh[MROWS * DMODEL], s_kl[MROWS * DMODEL];
__device__ __nv_bfloat16 s_vh[MROWS * DMODEL], s_vl[MROWS * DMODEL];
__device__ __nv_bfloat16 s_ch[MROWS * DMODEL], s_cl[MROWS * DMODEL];
__device__ __nv_bfloat16 s_wh[4][DMODEL * DMODEL], s_wl[4][DMODEL * DMODEL];

// attention operands (head layout / transposed), bf16 hi+lo
__device__ __nv_bfloat16 a_qh[BHN * SEQ * DK], a_ql[BHN * SEQ * DK];
__device__ __nv_bfloat16 a_kh[BHN * SEQ * DK], a_kl[BHN * SEQ * DK];
__device__ __nv_bfloat16 a_vth[BHN * DK * SEQ], a_vtl[BHN * DK * SEQ];

// ---------------- helpers ---------------------------------------------------
static __device__ __forceinline__ uint32_t smem_u32(const void* p) {
    uint32_t a;
    asm("{ .reg .u64 t; cvta.to.shared.u64 t, %1; cvt.u32.u64 %0, t; }"
        : "=r"(a) : "l"(p));
    return a;
}
static __device__ __forceinline__ void cp16(uint32_t s, const void* g) {
    asm volatile("cp.async.cg.shared.global [%0], [%1], 16;" :: "r"(s), "l"(g));
}
#define CP_COMMIT() asm volatile("cp.async.commit_group;")
template <int N>
static __device__ __forceinline__ void cp_wait() {
    asm volatile("cp.async.wait_group %0;" :: "n"(N));
}
static __device__ __forceinline__ void ldm_x4(uint32_t& r0, uint32_t& r1,
                                              uint32_t& r2, uint32_t& r3, uint32_t a) {
    asm volatile("ldmatrix.sync.aligned.m8n8.x4.shared.b16 {%0,%1,%2,%3}, [%4];"
                 : "=r"(r0), "=r"(r1), "=r"(r2), "=r"(r3) : "r"(a));
}
static __device__ __forceinline__ void mma_bf16(float* c, const uint32_t* a,
                                                const uint32_t* b) {
    asm volatile(
        "mma.sync.aligned.m16n8k16.row.col.f32.bf16.bf16.f32 "
        "{%0,%1,%2,%3}, {%4,%5,%6,%7}, {%8,%9}, {%0,%1,%2,%3};"
        : "+f"(c[0]), "+f"(c[1]), "+f"(c[2]), "+f"(c[3])
        : "r"(a[0]), "r"(a[1]), "r"(a[2]), "r"(a[3]), "r"(b[0]), "r"(b[1]));
}
static __device__ __forceinline__ float ex2(float x) {
    float y; asm("ex2.approx.f32 %0, %1;" : "=f"(y) : "f"(x)); return y;
}
static __device__ __forceinline__ void packhl(float a, float b,
                                              uint32_t& hi, uint32_t& lo) {
    __nv_bfloat16 ah = __float2bfloat16(a), bh = __float2bfloat16(b);
    __nv_bfloat16 al = __float2bfloat16(a - __bfloat162float(ah));
    __nv_bfloat16 bl = __float2bfloat16(b - __bfloat162float(bh));
    __nv_bfloat162 h2; h2.x = ah; h2.y = bh;
    __nv_bfloat162 l2; l2.x = al; l2.y = bl;
    hi = *(uint32_t*)&h2; lo = *(uint32_t*)&l2;
}

// ---------------------------------------------------------------------------
// split fp32 -> bf16 hi + bf16 lo  (R5 passing version, unchanged)
// ---------------------------------------------------------------------------
__global__ void split_kernel(const float* __restrict__ x,
                             __nv_bfloat16* __restrict__ hi,
                             __nv_bfloat16* __restrict__ lo, int n4)
{
    int i = blockIdx.x * 256 + threadIdx.x;
    if (i >= n4) return;
    float4 v = ((const float4*)x)[i];
    uint32_t h2[2], l2[2];
    packhl(v.x, v.y, h2[0], l2[0]);
    packhl(v.z, v.w, h2[1], l2[1]);
    ((uint32_t*)hi)[2 * i] = h2[0];
    ((uint32_t*)hi)[2 * i + 1] = h2[1];
    ((uint32_t*)lo)[2 * i] = l2[0];
    ((uint32_t*)lo)[2 * i + 1] = l2[1];
}

// ---------------------------------------------------------------------------
// Split-bf16 GEMM, 256x128 CTA tile (4m x 2n warps, warp 64x64), BK=32.
// Stage layout (48KB): Ah 16K | Al 16K | Bh 8K | Bl 8K.  192 MMAs per stage
// per warp.  3-stage cp.async pipeline with R5's proven stage bookkeeping.
// Epilogue modes: 0 fp32 flat, 1 bf16 hi/lo head layout, 2 bf16 hi/lo
// transposed [((b*H+h)*64+d)*SEQ+s].
// ---------------------------------------------------------------------------
#define NIT2 32      // 1024 / 32
#define GSTG 49152   // 48KB per stage

template <int MODE>
__global__ void __launch_bounds__(256, 1)
gemm_mma(const __nv_bfloat16* __restrict__ Ah, const __nv_bfloat16* __restrict__ Al,
         const __nv_bfloat16* __restrict__ Bh, const __nv_bfloat16* __restrict__ Bl,
         const float* __restrict__ bias, float* __restrict__ Y,
         __nv_bfloat16* __restrict__ Yh, __nv_bfloat16* __restrict__ Yl)
{
    extern __shared__ __align__(128) char dsm[];
    const uint32_t sS = smem_u32(dsm);     // 3 stages x 48KB

    const int tid = threadIdx.x;
    const int wid = tid >> 5, lane = tid & 31;
    const int wm = wid >> 1, wn = wid & 1;      // 4m x 2n
    const int m0 = blockIdx.y << 8, n0 = blockIdx.x << 7;

    float acc[4][8][4];
#pragma unroll
    for (int i = 0; i < 4; i++)
#pragma unroll
        for (int j = 0; j < 8; j++)
#pragma unroll
            for (int u = 0; u < 4; u++) acc[i][j][u] = 0.0f;

    const int lc = tid & 3;                 // 16B chunk within 64B row

    auto load_it = [&](int it2, int st) {
        const int kk = it2 << 5;            // k offset (bf16 elems)
        uint32_t b = sS + (uint32_t)st * GSTG;
        // A: 256 rows x 4 chunks, hi and lo
#pragma unroll
        for (int j = 0; j < 4; j++) {
            int cid = tid + 256 * j;        // 0..1023
            int row = cid >> 2;             // 0..255
            uint32_t off = (uint32_t)(row * 64 + ((lc ^ (row & 3)) << 4));
            size_t ga = (size_t)(m0 + row) * DMODEL + kk + lc * 8;
            cp16(b + off, Ah + ga);
            cp16(b + 16384u + off, Al + ga);
        }
        // B: 128 rows x 4 chunks, hi and lo
#pragma unroll
        for (int j = 0; j < 2; j++) {
            int cid = tid + 256 * j;        // 0..511
            int row = cid >> 2;             // 0..127
            uint32_t off = (uint32_t)(row * 64 + ((lc ^ (row & 3)) << 4));
            size_t gb = (size_t)(n0 + row) * DMODEL + kk + lc * 8;
            cp16(b + 32768u + off, Bh + gb);
            cp16(b + 40960u + off, Bl + gb);
        }
        CP_COMMIT();
    };

    const int arow = wm * 64 + (lane & 15);
    const int abit = lane >> 4;
    const int brow = wn * 64 + (lane & 7) + ((lane >> 4) & 1) * 8;
    const int bbit = (lane >> 3) & 1;

    load_it(0, 0);
    load_it(1, 1);

    int st = 0;   // stage of iteration `it`
    for (int it = 0; it < NIT2; ++it) {
        if (it + 1 < NIT2) cp_wait<1>(); else cp_wait<0>();
        __syncthreads();
        if (it + 2 < NIT2) {
            int st2 = st + 2; if (st2 >= 3) st2 -= 3;
            load_it(it + 2, st2);
        }

        const uint32_t sb = sS + (uint32_t)st * GSTG;

#pragma unroll
        for (int ks = 0; ks < 2; ks++) {
            uint32_t bh4[4][4], bl4[4][4];
#pragma unroll
            for (int np = 0; np < 4; np++) {
                int row = brow + np * 16;          // 0..127
                int ch = 2 * ks + bbit;
                uint32_t off = (uint32_t)(row * 64 + ((ch ^ (row & 3)) << 4));
                ldm_x4(bh4[np][0], bh4[np][1], bh4[np][2], bh4[np][3], sb + 32768u + off);
                ldm_x4(bl4[np][0], bl4[np][1], bl4[np][2], bl4[np][3], sb + 40960u + off);
            }
            uint32_t af[4][4];
#pragma unroll
            for (int mt = 0; mt < 4; mt++) {
                int row = arow + mt * 16;          // 0..255
                int ch = 2 * ks + abit;
                uint32_t ad = sb + (uint32_t)(row * 64 + ((ch ^ (row & 3)) << 4));
                ldm_x4(af[mt][0], af[mt][1], af[mt][2], af[mt][3], ad);
            }
#pragma unroll
            for (int mt = 0; mt < 4; mt++)
#pragma unroll
                for (int nn = 0; nn < 8; nn++)
                    mma_bf16(acc[mt][nn], af[mt], bh4[nn >> 1] + (nn & 1) * 2);
#pragma unroll
            for (int mt = 0; mt < 4; mt++)
#pragma unroll
                for (int nn = 0; nn < 8; nn++)
                    mma_bf16(acc[mt][nn], af[mt], bl4[nn >> 1] + (nn & 1) * 2);
            // reuse af registers for Al pass
#pragma unroll
            for (int mt = 0; mt < 4; mt++) {
                int row = arow + mt * 16;
                int ch = 2 * ks + abit;
                uint32_t ad = sb + 16384u + (uint32_t)(row * 64 + ((ch ^ (row & 3)) << 4));
                ldm_x4(af[mt][0], af[mt][1], af[mt][2], af[mt][3], ad);
            }
#pragma unroll
            for (int mt = 0; mt < 4; mt++)
#pragma unroll
                for (int nn = 0; nn < 8; nn++)
                    mma_bf16(acc[mt][nn], af[mt], bh4[nn >> 1] + (nn & 1) * 2);
        }
        if (++st == 3) st = 0;
    }

    // ---- epilogue ----
    const int ml = lane >> 2;
    const int nl = (lane & 3) << 1;
#pragma unroll
    for (int mt = 0; mt < 4; mt++) {
#pragma unroll
        for (int half = 0; half < 2; half++) {
            int m = m0 + wm * 64 + mt * 16 + ml + half * 8;
#pragma unroll
            for (int nn = 0; nn < 8; nn++) {
                int n = n0 + wn * 64 + nn * 8 + nl;
                float x = acc[mt][nn][2 * half + 0] + bias[n + 0];
                float y = acc[mt][nn][2 * half + 1] + bias[n + 1];
                if (MODE == 0) {
                    float2 o; o.x = x; o.y = y;
                    *(float2*)&Y[(size_t)m * DMODEL + n] = o;
                } else {
                    int bb = m >> 11, s = m & 2047;
                    int h = n >> 6, d = n & 63;
                    uint32_t hi, lo;
                    packhl(x, y, hi, lo);
                    if (MODE == 1) {
                        size_t idx = (size_t)((bb * H + h) * SEQ + s) * DK + d;
                        *(uint32_t*)&Yh[idx] = hi;
                        *(uint32_t*)&Yl[idx] = lo;
                    } else {
                        __nv_bfloat162 h2 = *(__nv_bfloat162*)&hi;
                        __nv_bfloat162 l2 = *(__nv_bfloat162*)&lo;
                        size_t base = (size_t)((bb * H + h) * DK + d) * SEQ + s;
                        Yh[base] = h2.x; Yh[base + SEQ] = h2.y;
                        Yl[base] = l2.x; Yl[base + SEQ] = l2.y;
                    }
                }
            }
        }
    }
}

// ---------------------------------------------------------------------------
// Tensor-core flash attention, split-bf16 (R5 passing version, unchanged)
// ---------------------------------------------------------------------------
__global__ void __launch_bounds__(256)
attn_mma()
{
    extern __shared__ __align__(128) char dsm[];
    const uint32_t sbase = smem_u32(dsm);
    const uint32_t sQh = sbase, sQl = sbase + 16384;
    const uint32_t sKV = sbase + 32768;

    const int bh = blockIdx.x;
    const int q0 = blockIdx.y << 7;
    const int tid = threadIdx.x, wid = tid >> 5, lane = tid & 31;

    const __nv_bfloat16* qhg = a_qh + (size_t)bh * SEQ * DK;
    const __nv_bfloat16* qlg = a_ql + (size_t)bh * SEQ * DK;
    const __nv_bfloat16* khg = a_kh + (size_t)bh * SEQ * DK;
    const __nv_bfloat16* klg = a_kl + (size_t)bh * SEQ * DK;
    const __nv_bfloat16* vhg = a_vth + (size_t)bh * DK * SEQ;
    const __nv_bfloat16* vlg = a_vtl + (size_t)bh * DK * SEQ;

#pragma unroll
    for (int j = 0; j < 4; j++) {
        int cid = tid + 256 * j;
        int hr = cid >> 2, c = cid & 3;
        int qrow = hr & 127, panel = hr >> 7;
        uint32_t off = (uint32_t)(hr * 64 + ((c ^ (hr & 3)) << 4));
        const size_t src = (size_t)(q0 + qrow) * DK + panel * 32 + c * 8;
        cp16(sQh + off, qhg + src);
        cp16(sQl + off, qlg + src);
    }
    CP_COMMIT();
    cp_wait<0>();
    __syncthreads();

    uint32_t fQh[4][4], fQl[4][4];
    {
        const int row = wid * 16 + (lane & 15);
#pragma unroll
        for (int kf = 0; kf < 4; kf++) {
            int ch = ((kf & 1) << 1) + (lane >> 4);
            uint32_t off = (uint32_t)((kf >> 1) * 8192 + row * 64 + ((ch ^ (row & 3)) << 4));
            ldm_x4(fQh[kf][0], fQh[kf][1], fQh[kf][2], fQh[kf][3], sQh + off);
            ldm_x4(fQl[kf][0], fQl[kf][1], fQl[kf][2], fQl[kf][3], sQl + off);
        }
    }

    float ctxa[8][4];
#pragma unroll
    for (int i = 0; i < 8; i++)
#pragma unroll
        for (int u = 0; u < 4; u++) ctxa[i][u] = 0.0f;
    float mrun[2] = {-1e30f, -1e30f};
    float lrun[2] = {0.0f, 0.0f};

    auto load_kv = [&](int kt, int buf) {
        uint32_t base = sKV + buf * 32768;
#pragma unroll
        for (int j = 0; j < 2; j++) {
            int cid = tid + 256 * j;
            int hr = cid >> 2, c = cid & 3;
            uint32_t off = (uint32_t)(hr * 64 + ((c ^ (hr & 3)) << 4));
            int lo6 = hr & 63, pan = hr >> 6;
            size_t ksrc = (size_t)(kt + lo6) * DK + pan * 32 + c * 8;
            size_t vsrc = (size_t)lo6 * SEQ + kt + pan * 32 + c * 8;
            cp16(base + off, khg + ksrc);
            cp16(base + 8192 + off, klg + ksrc);
            cp16(base + 16384 + off, vhg + vsrc);
            cp16(base + 24576 + off, vlg + vsrc);
        }
        CP_COMMIT();
    };

    const int brow = (lane & 7) + ((lane >> 4) & 1) * 8;
    const int bbit = (lane >> 3) & 1;
    const float C2 = 0.18033688f;

    load_kv(0, 0);

    for (int t = 0; t < SEQ / 64; ++t) {
        if (t + 1 < SEQ / 64) { load_kv((t + 1) * 64, (t + 1) & 1); cp_wait<1>(); }
        else cp_wait<0>();
        __syncthreads();

        const uint32_t base = sKV + (t & 1) * 32768;

        float sacc[8][4];
#pragma unroll
        for (int i = 0; i < 8; i++)
#pragma unroll
            for (int u = 0; u < 4; u++) sacc[i][u] = 0.0f;

#pragma unroll
        for (int kf = 0; kf < 4; kf++) {
#pragma unroll
            for (int np = 0; np < 4; np++) {
                int row = np * 16 + brow;
                int ch = ((kf & 1) << 1) + bbit;
                uint32_t off = (uint32_t)((kf >> 1) * 4096 + row * 64 + ((ch ^ (row & 3)) << 4));
                uint32_t kh4[4], kl4[4];
                ldm_x4(kh4[0], kh4[1], kh4[2], kh4[3], base + off);
                ldm_x4(kl4[0], kl4[1], kl4[2], kl4[3], base + 8192 + off);
                mma_bf16(sacc[2 * np], fQh[kf], kh4 + 0);
                mma_bf16(sacc[2 * np + 1], fQh[kf], kh4 + 2);
                mma_bf16(sacc[2 * np], fQl[kf], kh4 + 0);
                mma_bf16(sacc[2 * np + 1], fQl[kf], kh4 + 2);
                mma_bf16(sacc[2 * np], fQh[kf], kl4 + 0);
                mma_bf16(sacc[2 * np + 1], fQh[kf], kl4 + 2);
            }
        }

        float rmax0 = -1e30f, rmax1 = -1e30f;
#pragma unroll
        for (int i = 0; i < 8; i++) {
            rmax0 = fmaxf(rmax0, fmaxf(sacc[i][0], sacc[i][1]));
            rmax1 = fmaxf(rmax1, fmaxf(sacc[i][2], sacc[i][3]));
        }
        rmax0 = fmaxf(rmax0, __shfl_xor_sync(0xffffffffu, rmax0, 1));
        rmax0 = fmaxf(rmax0, __shfl_xor_sync(0xffffffffu, rmax0, 2));
        rmax1 = fmaxf(rmax1, __shfl_xor_sync(0xffffffffu, rmax1, 1));
        rmax1 = fmaxf(rmax1, __shfl_xor_sync(0xffffffffu, rmax1, 2));
        float mn0 = fmaxf(mrun[0], C2 * rmax0);
        float mn1 = fmaxf(mrun[1], C2 * rmax1);
        float al0 = ex2(mrun[0] - mn0);
        float al1 = ex2(mrun[1] - mn1);
        mrun[0] = mn0; mrun[1] = mn1;
#pragma unroll
        for (int i = 0; i < 8; i++) {
            ctxa[i][0] *= al0; ctxa[i][1] *= al0;
            ctxa[i][2] *= al1; ctxa[i][3] *= al1;
        }
        float rs0 = 0.0f, rs1 = 0.0f;
#pragma unroll
        for (int i = 0; i < 8; i++) {
            sacc[i][0] = ex2(fmaf(C2, sacc[i][0], -mn0));
            sacc[i][1] = ex2(fmaf(C2, sacc[i][1], -mn0));
            sacc[i][2] = ex2(fmaf(C2, sacc[i][2], -mn1));
            sacc[i][3] = ex2(fmaf(C2, sacc[i][3], -mn1));
            rs0 += sacc[i][0] + sacc[i][1];
            rs1 += sacc[i][2] + sacc[i][3];
        }
        rs0 += __shfl_xor_sync(0xffffffffu, rs0, 1);
        rs0 += __shfl_xor_sync(0xffffffffu, rs0, 2);
        rs1 += __shfl_xor_sync(0xffffffffu, rs1, 1);
        rs1 += __shfl_xor_sync(0xffffffffu, rs1, 2);
        lrun[0] = lrun[0] * al0 + rs0;
        lrun[1] = lrun[1] * al1 + rs1;

#pragma unroll
        for (int kf = 0; kf < 4; kf++) {
            uint32_t pH[4], pL[4];
            packhl(sacc[2 * kf][0], sacc[2 * kf][1], pH[0], pL[0]);
            packhl(sacc[2 * kf][2], sacc[2 * kf][3], pH[1], pL[1]);
            packhl(sacc[2 * kf + 1][0], sacc[2 * kf + 1][1], pH[2], pL[2]);
            packhl(sacc[2 * kf + 1][2], sacc[2 * kf + 1][3], pH[3], pL[3]);
#pragma unroll
            for (int np = 0; np < 4; np++) {
                int row = np * 16 + brow;
                int ch = ((kf & 1) << 1) + bbit;
                uint32_t off = (uint32_t)((kf >> 1) * 4096 + row * 64 + ((ch ^ (row & 3)) << 4));
                uint32_t vh4[4], vl4[4];
                ldm_x4(vh4[0], vh4[1], vh4[2], vh4[3], base + 16384 + off);
                ldm_x4(vl4[0], vl4[1], vl4[2], vl4[3], base + 24576 + off);
                mma_bf16(ctxa[2 * np], pH, vh4 + 0);
                mma_bf16(ctxa[2 * np + 1], pH, vh4 + 2);
                mma_bf16(ctxa[2 * np], pL, vh4 + 0);
                mma_bf16(ctxa[2 * np + 1], pL, vh4 + 2);
                mma_bf16(ctxa[2 * np], pH, vl4 + 0);
                mma_bf16(ctxa[2 * np + 1], pH, vl4 + 2);
            }
        }
        __syncthreads();
    }

    const float inv0 = 1.0f / lrun[0];
    const float inv1 = 1.0f / lrun[1];
    const int b = bh >> 4, h = bh & 15;
    const int r0 = q0 + wid * 16 + (lane >> 2);
    const int nl = (lane & 3) << 1;
#pragma unroll
    for (int nt = 0; nt < 8; nt++) {
        int d = nt * 8 + nl;
        uint32_t hi, lo;
        packhl(ctxa[nt][0] * inv0, ctxa[nt][1] * inv0, hi, lo);
        size_t i0 = (size_t)(b * SEQ + r0) * DMODEL + h * 64 + d;
        *(uint32_t*)&s_ch[i0] = hi;
        *(uint32_t*)&s_cl[i0] = lo;
        packhl(ctxa[nt][2] * inv1, ctxa[nt][3] * inv1, hi, lo);
        size_t i1 = (size_t)(b * SEQ + r0 + 8) * DMODEL + h * 64 + d;
        *(uint32_t*)&s_ch[i1] = hi;
        *(uint32_t*)&s_cl[i1] = lo;
    }
}

// ---------------------------------------------------------------------------
extern "C" void kernel_launch(void* const* d_in, const int* in_sizes, int n_in,
                              void* d_out, int out_size)
{
    (void)in_sizes; (void)n_in; (void)out_size;
    const float* q  = (const float*)d_in[0];
    const float* k  = (const float*)d_in[1];
    const float* v  = (const float*)d_in[2];
    const float* Wq = (const float*)d_in[3];
    const float* bq = (const float*)d_in[4];
    const float* Wk = (const float*)d_in[5];
    const float* bk = (const float*)d_in[6];
    const float* Wv = (const float*)d_in[7];
    const float* bv = (const float*)d_in[8];
    const float* Wo = (const float*)d_in[9];
    const float* bo = (const float*)d_in[10];
    float* out = (float*)d_out;

    __nv_bfloat16 *qh, *ql, *kh, *kl, *vh, *vl, *ch, *cl, *wh, *wl;
    __nv_bfloat16 *aqh, *aql, *akh, *akl, *avh, *avl;
    cudaGetSymbolAddress((void**)&qh, s_qh); cudaGetSymbolAddress((void**)&ql, s_ql);
    cudaGetSymbolAddress((void**)&kh, s_kh); cudaGetSymbolAddress((void**)&kl, s_kl);
    cudaGetSymbolAddress((void**)&vh, s_vh); cudaGetSymbolAddress((void**)&vl, s_vl);
    cudaGetSymbolAddress((void**)&ch, s_ch); cudaGetSymbolAddress((void**)&cl, s_cl);
    cudaGetSymbolAddress((void**)&wh, s_wh); cudaGetSymbolAddress((void**)&wl, s_wl);
    cudaGetSymbolAddress((void**)&aqh, a_qh); cudaGetSymbolAddress((void**)&aql, a_ql);
    cudaGetSymbolAddress((void**)&akh, a_kh); cudaGetSymbolAddress((void**)&akl, a_kl);
    cudaGetSymbolAddress((void**)&avh, a_vth); cudaGetSymbolAddress((void**)&avl, a_vtl);

    const int GSM = 3 * GSTG;   // 144KB
    cudaFuncSetAttribute(gemm_mma<0>, cudaFuncAttributeMaxDynamicSharedMemorySize, GSM);
    cudaFuncSetAttribute(gemm_mma<1>, cudaFuncAttributeMaxDynamicSharedMemorySize, GSM);
    cudaFuncSetAttribute(gemm_mma<2>, cudaFuncAttributeMaxDynamicSharedMemorySize, GSM);
    cudaFuncSetAttribute(attn_mma, cudaFuncAttributeMaxDynamicSharedMemorySize, 98304);

    const size_t WSZ = (size_t)DMODEL * DMODEL;
    const int NX4 = MROWS * DMODEL / 4;
    const int NW4 = DMODEL * DMODEL / 4;
    split_kernel<<<NX4 / 256, 256>>>(q, qh, ql, NX4);
    split_kernel<<<NX4 / 256, 256>>>(k, kh, kl, NX4);
    split_kernel<<<NX4 / 256, 256>>>(v, vh, vl, NX4);
    split_kernel<<<NW4 / 256, 256>>>(Wq, wh + 0 * WSZ, wl + 0 * WSZ, NW4);
    split_kernel<<<NW4 / 256, 256>>>(Wk, wh + 1 * WSZ, wl + 1 * WSZ, NW4);
    split_kernel<<<NW4 / 256, 256>>>(Wv, wh + 2 * WSZ, wl + 2 * WSZ, NW4);
    split_kernel<<<NW4 / 256, 256>>>(Wo, wh + 3 * WSZ, wl + 3 * WSZ, NW4);

    dim3 gg(DMODEL / 128, MROWS / 256);  // (8, 16)
    gemm_mma<1><<<gg, 256, GSM>>>(qh, ql, wh + 0 * WSZ, wl + 0 * WSZ, bq, nullptr, aqh, aql);
    gemm_mma<1><<<gg, 256, GSM>>>(kh, kl, wh + 1 * WSZ, wl + 1 * WSZ, bk, nullptr, akh, akl);
    gemm_mma<2><<<gg, 256, GSM>>>(vh, vl, wh + 2 * WSZ, wl + 2 * WSZ, bv, nullptr, avh, avl);

    attn_mma<<<dim3(BHN, SEQ / 128), 256, 98304>>>();

    gemm_mma<0><<<gg, 256, GSM>>>(ch, cl, wh + 3 * WSZ, wl + 3 * WSZ, bo, out, nullptr, nullptr);
}

// round 8
// speedup vs baseline: 1.4462x; 1.4462x over previous
#include <cuda_runtime.h>
#include <cuda_fp16.h>
#include <cstdint>
#include <math.h>

#define H 16
#define DMODEL 1024
#define DK 64
#define NB 2
#define SEQ 2048
#define MROWS (NB*SEQ)   // 4096
#define BHN (NB*H)       // 32

// ---------------- scratch (device globals; no allocation allowed) ----------
// activations split hi+lo (A-side of proj GEMMs)
__device__ __half s_qh[MROWS * DMODEL], s_ql[MROWS * DMODEL];
__device__ __half s_kh[MROWS * DMODEL], s_kl[MROWS * DMODEL];
__device__ __half s_vh[MROWS * DMODEL], s_vl[MROWS * DMODEL];
__device__ __half s_ch[MROWS * DMODEL], s_cl[MROWS * DMODEL];
// weights single fp16 (B-side)
__device__ __half s_w[4][DMODEL * DMODEL];
// attention operands: Q split (A-side), K / V^T single fp16 (B-side)
__device__ __half a_qh[BHN * SEQ * DK], a_ql[BHN * SEQ * DK];
__device__ __half a_k[BHN * SEQ * DK];
__device__ __half a_vt[BHN * DK * SEQ];

// ---------------- helpers ---------------------------------------------------
static __device__ __forceinline__ uint32_t smem_u32(const void* p) {
    uint32_t a;
    asm("{ .reg .u64 t; cvta.to.shared.u64 t, %1; cvt.u32.u64 %0, t; }"
        : "=r"(a) : "l"(p));
    return a;
}
static __device__ __forceinline__ void cp16(uint32_t s, const void* g) {
    asm volatile("cp.async.cg.shared.global [%0], [%1], 16;" :: "r"(s), "l"(g));
}
#define CP_COMMIT() asm volatile("cp.async.commit_group;")
template <int N>
static __device__ __forceinline__ void cp_wait() {
    asm volatile("cp.async.wait_group %0;" :: "n"(N));
}
static __device__ __forceinline__ void ldm_x4(uint32_t& r0, uint32_t& r1,
                                              uint32_t& r2, uint32_t& r3, uint32_t a) {
    asm volatile("ldmatrix.sync.aligned.m8n8.x4.shared.b16 {%0,%1,%2,%3}, [%4];"
                 : "=r"(r0), "=r"(r1), "=r"(r2), "=r"(r3) : "r"(a));
}
static __device__ __forceinline__ void mma_f16(float* c, const uint32_t* a,
                                               const uint32_t* b) {
    asm volatile(
        "mma.sync.aligned.m16n8k16.row.col.f32.f16.f16.f32 "
        "{%0,%1,%2,%3}, {%4,%5,%6,%7}, {%8,%9}, {%0,%1,%2,%3};"
        : "+f"(c[0]), "+f"(c[1]), "+f"(c[2]), "+f"(c[3])
        : "r"(a[0]), "r"(a[1]), "r"(a[2]), "r"(a[3]), "r"(b[0]), "r"(b[1]));
}
static __device__ __forceinline__ float ex2(float x) {
    float y; asm("ex2.approx.f32 %0, %1;" : "=f"(y) : "f"(x)); return y;
}
// pack two floats -> fp16x2 hi and fp16x2 lo (residual)
static __device__ __forceinline__ void packhl(float a, float b,
                                              uint32_t& hi, uint32_t& lo) {
    __half ah = __float2half_rn(a), bh = __float2half_rn(b);
    __half al = __float2half_rn(a - __half2float(ah));
    __half bl = __float2half_rn(b - __half2float(bh));
    __half2 h2 = __halves2half2(ah, bh);
    __half2 l2 = __halves2half2(al, bl);
    hi = *(uint32_t*)&h2; lo = *(uint32_t*)&l2;
}
static __device__ __forceinline__ uint32_t pack2h(float a, float b) {
    __half2 h2 = __halves2half2(__float2half_rn(a), __float2half_rn(b));
    return *(uint32_t*)&h2;
}

// ---------------------------------------------------------------------------
// split fp32 -> fp16 hi + fp16 lo  (activations)
// ---------------------------------------------------------------------------
__global__ void split_kernel(const float* __restrict__ x,
                             __half* __restrict__ hi,
                             __half* __restrict__ lo, int n4)
{
    int i = blockIdx.x * 256 + threadIdx.x;
    if (i >= n4) return;
    float4 v = ((const float4*)x)[i];
    uint32_t h2[2], l2[2];
    packhl(v.x, v.y, h2[0], l2[0]);
    packhl(v.z, v.w, h2[1], l2[1]);
    ((uint32_t*)hi)[2 * i] = h2[0];
    ((uint32_t*)hi)[2 * i + 1] = h2[1];
    ((uint32_t*)lo)[2 * i] = l2[0];
    ((uint32_t*)lo)[2 * i + 1] = l2[1];
}
// convert fp32 -> single fp16  (weights)
__global__ void cvt_kernel(const float* __restrict__ x,
                           __half* __restrict__ yh, int n4)
{
    int i = blockIdx.x * 256 + threadIdx.x;
    if (i >= n4) return;
    float4 v = ((const float4*)x)[i];
    ((uint32_t*)yh)[2 * i] = pack2h(v.x, v.y);
    ((uint32_t*)yh)[2 * i + 1] = pack2h(v.z, v.w);
}

// ---------------------------------------------------------------------------
// fp16 2-pass GEMM: Y = (Ah + Al) @ B^T + bias.  256x128 CTA tile
// (4m x 2n warps, warp 64x64), BK=32.  Stage (40KB): Ah 16K | Al 16K | B 8K.
// 128 MMAs per stage per warp.  3-stage cp.async pipeline (R7 skeleton).
// Epilogue modes: 0 fp32 flat | 1 head hi+lo | 2 transposed hi | 3 head hi.
// ---------------------------------------------------------------------------
#define NIT2 32      // 1024 / 32
#define GSTG 40960   // 40KB per stage

template <int MODE>
__global__ void __launch_bounds__(256, 1)
gemm_mma(const __half* __restrict__ Ah, const __half* __restrict__ Al,
         const __half* __restrict__ B,
         const float* __restrict__ bias, float* __restrict__ Y,
         __half* __restrict__ Yh, __half* __restrict__ Yl)
{
    extern __shared__ __align__(128) char dsm[];
    const uint32_t sS = smem_u32(dsm);     // 3 stages x 40KB

    const int tid = threadIdx.x;
    const int wid = tid >> 5, lane = tid & 31;
    const int wm = wid >> 1, wn = wid & 1;      // 4m x 2n
    const int m0 = blockIdx.y << 8, n0 = blockIdx.x << 7;

    float acc[4][8][4];
#pragma unroll
    for (int i = 0; i < 4; i++)
#pragma unroll
        for (int j = 0; j < 8; j++)
#pragma unroll
            for (int u = 0; u < 4; u++) acc[i][j][u] = 0.0f;

    const int lc = tid & 3;                 // 16B chunk within 64B row

    auto load_it = [&](int it2, int st) {
        const int kk = it2 << 5;            // k offset (fp16 elems)
        uint32_t b = sS + (uint32_t)st * GSTG;
        // A: 256 rows x 4 chunks, hi and lo
#pragma unroll
        for (int j = 0; j < 4; j++) {
            int cid = tid + 256 * j;        // 0..1023
            int row = cid >> 2;             // 0..255
            uint32_t off = (uint32_t)(row * 64 + ((lc ^ (row & 3)) << 4));
            size_t ga = (size_t)(m0 + row) * DMODEL + kk + lc * 8;
            cp16(b + off, Ah + ga);
            cp16(b + 16384u + off, Al + ga);
        }
        // B: 128 rows x 4 chunks, hi only
        {
            int cid = tid + 256;            // two halves: tid, tid+256 -> 512
        }
#pragma unroll
        for (int j = 0; j < 2; j++) {
            int cid = tid + 256 * j;        // 0..511
            int row = cid >> 2;             // 0..127
            uint32_t off = (uint32_t)(row * 64 + ((lc ^ (row & 3)) << 4));
            size_t gb = (size_t)(n0 + row) * DMODEL + kk + lc * 8;
            cp16(b + 32768u + off, B + gb);
        }
        CP_COMMIT();
    };

    const int arow = wm * 64 + (lane & 15);
    const int abit = lane >> 4;
    const int brow = wn * 64 + (lane & 7) + ((lane >> 4) & 1) * 8;
    const int bbit = (lane >> 3) & 1;

    load_it(0, 0);
    load_it(1, 1);

    int st = 0;
    for (int it = 0; it < NIT2; ++it) {
        if (it + 1 < NIT2) cp_wait<1>(); else cp_wait<0>();
        __syncthreads();
        if (it + 2 < NIT2) {
            int st2 = st + 2; if (st2 >= 3) st2 -= 3;
            load_it(it + 2, st2);
        }

        const uint32_t sb = sS + (uint32_t)st * GSTG;

#pragma unroll
        for (int ks = 0; ks < 2; ks++) {
            uint32_t bh4[4][4];
#pragma unroll
            for (int np = 0; np < 4; np++) {
                int row = brow + np * 16;          // 0..127
                int ch = 2 * ks + bbit;
                uint32_t off = (uint32_t)(row * 64 + ((ch ^ (row & 3)) << 4));
                ldm_x4(bh4[np][0], bh4[np][1], bh4[np][2], bh4[np][3], sb + 32768u + off);
            }
            uint32_t af[4][4];
#pragma unroll
            for (int mt = 0; mt < 4; mt++) {
                int row = arow + mt * 16;          // 0..255
                int ch = 2 * ks + abit;
                uint32_t ad = sb + (uint32_t)(row * 64 + ((ch ^ (row & 3)) << 4));
                ldm_x4(af[mt][0], af[mt][1], af[mt][2], af[mt][3], ad);
            }
#pragma unroll
            for (int mt = 0; mt < 4; mt++)
#pragma unroll
                for (int nn = 0; nn < 8; nn++)
                    mma_f16(acc[mt][nn], af[mt], bh4[nn >> 1] + (nn & 1) * 2);
            // reuse af registers for Al pass
#pragma unroll
            for (int mt = 0; mt < 4; mt++) {
                int row = arow + mt * 16;
                int ch = 2 * ks + abit;
                uint32_t ad = sb + 16384u + (uint32_t)(row * 64 + ((ch ^ (row & 3)) << 4));
                ldm_x4(af[mt][0], af[mt][1], af[mt][2], af[mt][3], ad);
            }
#pragma unroll
            for (int mt = 0; mt < 4; mt++)
#pragma unroll
                for (int nn = 0; nn < 8; nn++)
                    mma_f16(acc[mt][nn], af[mt], bh4[nn >> 1] + (nn & 1) * 2);
        }
        if (++st == 3) st = 0;
    }

    // ---- epilogue ----
    const int ml = lane >> 2;
    const int nl = (lane & 3) << 1;
#pragma unroll
    for (int mt = 0; mt < 4; mt++) {
#pragma unroll
        for (int half = 0; half < 2; half++) {
            int m = m0 + wm * 64 + mt * 16 + ml + half * 8;
#pragma unroll
            for (int nn = 0; nn < 8; nn++) {
                int n = n0 + wn * 64 + nn * 8 + nl;
                float x = acc[mt][nn][2 * half + 0] + bias[n + 0];
                float y = acc[mt][nn][2 * half + 1] + bias[n + 1];
                if (MODE == 0) {
                    float2 o; o.x = x; o.y = y;
                    *(float2*)&Y[(size_t)m * DMODEL + n] = o;
                } else {
                    int bb = m >> 11, s = m & 2047;
                    int h = n >> 6, d = n & 63;
                    if (MODE == 1) {
                        uint32_t hi, lo;
                        packhl(x, y, hi, lo);
                        size_t idx = (size_t)((bb * H + h) * SEQ + s) * DK + d;
                        *(uint32_t*)&Yh[idx] = hi;
                        *(uint32_t*)&Yl[idx] = lo;
                    } else if (MODE == 3) {
                        size_t idx = (size_t)((bb * H + h) * SEQ + s) * DK + d;
                        *(uint32_t*)&Yh[idx] = pack2h(x, y);
                    } else {
                        size_t base = (size_t)((bb * H + h) * DK + d) * SEQ + s;
                        Yh[base] = __float2half_rn(x);
                        Yh[base + SEQ] = __float2half_rn(y);
                    }
                }
            }
        }
    }
}

// ---------------------------------------------------------------------------
// fp16 2-pass flash attention.  BQ=128, BKV=64, 8 warps x 16 q-rows.
// Q split (hi+lo frags resident); K / V^T single fp16, double-buffered.
// Smem: Qh 16K | Ql 16K | 2 x (K 8K | V 8K) = 64KB.
// S = (Qh+Ql)*K ; ctx += (Ph+Pl)*V.
// ---------------------------------------------------------------------------
__global__ void __launch_bounds__(256)
attn_mma()
{
    extern __shared__ __align__(128) char dsm[];
    const uint32_t sbase = smem_u32(dsm);
    const uint32_t sQh = sbase, sQl = sbase + 16384;
    const uint32_t sKV = sbase + 32768;           // + buf*16384

    const int bh = blockIdx.x;
    const int q0 = blockIdx.y << 7;
    const int tid = threadIdx.x, wid = tid >> 5, lane = tid & 31;

    const __half* qhg = a_qh + (size_t)bh * SEQ * DK;
    const __half* qlg = a_ql + (size_t)bh * SEQ * DK;
    const __half* kg = a_k + (size_t)bh * SEQ * DK;
    const __half* vg = a_vt + (size_t)bh * DK * SEQ;

#pragma unroll
    for (int j = 0; j < 4; j++) {
        int cid = tid + 256 * j;
        int hr = cid >> 2, c = cid & 3;
        int qrow = hr & 127, panel = hr >> 7;
        uint32_t off = (uint32_t)(hr * 64 + ((c ^ (hr & 3)) << 4));
        const size_t src = (size_t)(q0 + qrow) * DK + panel * 32 + c * 8;
        cp16(sQh + off, qhg + src);
        cp16(sQl + off, qlg + src);
    }
    CP_COMMIT();
    cp_wait<0>();
    __syncthreads();

    uint32_t fQh[4][4], fQl[4][4];
    {
        const int row = wid * 16 + (lane & 15);
#pragma unroll
        for (int kf = 0; kf < 4; kf++) {
            int ch = ((kf & 1) << 1) + (lane >> 4);
            uint32_t off = (uint32_t)((kf >> 1) * 8192 + row * 64 + ((ch ^ (row & 3)) << 4));
            ldm_x4(fQh[kf][0], fQh[kf][1], fQh[kf][2], fQh[kf][3], sQh + off);
            ldm_x4(fQl[kf][0], fQl[kf][1], fQl[kf][2], fQl[kf][3], sQl + off);
        }
    }

    float ctxa[8][4];
#pragma unroll
    for (int i = 0; i < 8; i++)
#pragma unroll
        for (int u = 0; u < 4; u++) ctxa[i][u] = 0.0f;
    float mrun[2] = {-1e30f, -1e30f};
    float lrun[2] = {0.0f, 0.0f};

    auto load_kv = [&](int kt, int buf) {
        uint32_t base = sKV + buf * 16384;
#pragma unroll
        for (int j = 0; j < 2; j++) {
            int cid = tid + 256 * j;
            int hr = cid >> 2, c = cid & 3;
            uint32_t off = (uint32_t)(hr * 64 + ((c ^ (hr & 3)) << 4));
            int lo6 = hr & 63, pan = hr >> 6;
            size_t ksrc = (size_t)(kt + lo6) * DK + pan * 32 + c * 8;
            size_t vsrc = (size_t)lo6 * SEQ + kt + pan * 32 + c * 8;
            cp16(base + off, kg + ksrc);
            cp16(base + 8192 + off, vg + vsrc);
        }
        CP_COMMIT();
    };

    const int brow = (lane & 7) + ((lane >> 4) & 1) * 8;
    const int bbit = (lane >> 3) & 1;
    const float C2 = 0.18033688f;   // log2(e)/8

    load_kv(0, 0);

    for (int t = 0; t < SEQ / 64; ++t) {
        if (t + 1 < SEQ / 64) { load_kv((t + 1) * 64, (t + 1) & 1); cp_wait<1>(); }
        else cp_wait<0>();
        __syncthreads();

        const uint32_t base = sKV + (t & 1) * 16384;

        // ---- S = (Qh + Ql) * K ----
        float sacc[8][4];
#pragma unroll
        for (int i = 0; i < 8; i++)
#pragma unroll
            for (int u = 0; u < 4; u++) sacc[i][u] = 0.0f;

#pragma unroll
        for (int kf = 0; kf < 4; kf++) {
#pragma unroll
            for (int np = 0; np < 4; np++) {
                int row = np * 16 + brow;
                int ch = ((kf & 1) << 1) + bbit;
                uint32_t off = (uint32_t)((kf >> 1) * 4096 + row * 64 + ((ch ^ (row & 3)) << 4));
                uint32_t kh4[4];
                ldm_x4(kh4[0], kh4[1], kh4[2], kh4[3], base + off);
                mma_f16(sacc[2 * np], fQh[kf], kh4 + 0);
                mma_f16(sacc[2 * np + 1], fQh[kf], kh4 + 2);
                mma_f16(sacc[2 * np], fQl[kf], kh4 + 0);
                mma_f16(sacc[2 * np + 1], fQl[kf], kh4 + 2);
            }
        }

        // ---- online softmax (base-2) ----
        float rmax0 = -1e30f, rmax1 = -1e30f;
#pragma unroll
        for (int i = 0; i < 8; i++) {
            rmax0 = fmaxf(rmax0, fmaxf(sacc[i][0], sacc[i][1]));
            rmax1 = fmaxf(rmax1, fmaxf(sacc[i][2], sacc[i][3]));
        }
        rmax0 = fmaxf(rmax0, __shfl_xor_sync(0xffffffffu, rmax0, 1));
        rmax0 = fmaxf(rmax0, __shfl_xor_sync(0xffffffffu, rmax0, 2));
        rmax1 = fmaxf(rmax1, __shfl_xor_sync(0xffffffffu, rmax1, 1));
        rmax1 = fmaxf(rmax1, __shfl_xor_sync(0xffffffffu, rmax1, 2));
        float mn0 = fmaxf(mrun[0], C2 * rmax0);
        float mn1 = fmaxf(mrun[1], C2 * rmax1);
        float al0 = ex2(mrun[0] - mn0);
        float al1 = ex2(mrun[1] - mn1);
        mrun[0] = mn0; mrun[1] = mn1;
#pragma unroll
        for (int i = 0; i < 8; i++) {
            ctxa[i][0] *= al0; ctxa[i][1] *= al0;
            ctxa[i][2] *= al1; ctxa[i][3] *= al1;
        }
        float rs0 = 0.0f, rs1 = 0.0f;
#pragma unroll
        for (int i = 0; i < 8; i++) {
            sacc[i][0] = ex2(fmaf(C2, sacc[i][0], -mn0));
            sacc[i][1] = ex2(fmaf(C2, sacc[i][1], -mn0));
            sacc[i][2] = ex2(fmaf(C2, sacc[i][2], -mn1));
            sacc[i][3] = ex2(fmaf(C2, sacc[i][3], -mn1));
            rs0 += sacc[i][0] + sacc[i][1];
            rs1 += sacc[i][2] + sacc[i][3];
        }
        rs0 += __shfl_xor_sync(0xffffffffu, rs0, 1);
        rs0 += __shfl_xor_sync(0xffffffffu, rs0, 2);
        rs1 += __shfl_xor_sync(0xffffffffu, rs1, 1);
        rs1 += __shfl_xor_sync(0xffffffffu, rs1, 2);
        lrun[0] = lrun[0] * al0 + rs0;
        lrun[1] = lrun[1] * al1 + rs1;

        // ---- ctx += (Ph + Pl) * V ----
#pragma unroll
        for (int kf = 0; kf < 4; kf++) {
            uint32_t pH[4], pL[4];
            packhl(sacc[2 * kf][0], sacc[2 * kf][1], pH[0], pL[0]);
            packhl(sacc[2 * kf][2], sacc[2 * kf][3], pH[1], pL[1]);
            packhl(sacc[2 * kf + 1][0], sacc[2 * kf + 1][1], pH[2], pL[2]);
            packhl(sacc[2 * kf + 1][2], sacc[2 * kf + 1][3], pH[3], pL[3]);
#pragma unroll
            for (int np = 0; np < 4; np++) {
                int row = np * 16 + brow;
                int ch = ((kf & 1) << 1) + bbit;
                uint32_t off = (uint32_t)((kf >> 1) * 4096 + row * 64 + ((ch ^ (row & 3)) << 4));
                uint32_t vh4[4];
                ldm_x4(vh4[0], vh4[1], vh4[2], vh4[3], base + 8192 + off);
                mma_f16(ctxa[2 * np], pH, vh4 + 0);
                mma_f16(ctxa[2 * np + 1], pH, vh4 + 2);
                mma_f16(ctxa[2 * np], pL, vh4 + 0);
                mma_f16(ctxa[2 * np + 1], pL, vh4 + 2);
            }
        }
        __syncthreads();
    }

    // ---- epilogue: ctx/l -> fp16 hi/lo flat [b*S+s][h*64+d] ----
    const float inv0 = 1.0f / lrun[0];
    const float inv1 = 1.0f / lrun[1];
    const int b = bh >> 4, h = bh & 15;
    const int r0 = q0 + wid * 16 + (lane >> 2);
    const int nl = (lane & 3) << 1;
#pragma unroll
    for (int nt = 0; nt < 8; nt++) {
        int d = nt * 8 + nl;
        uint32_t hi, lo;
        packhl(ctxa[nt][0] * inv0, ctxa[nt][1] * inv0, hi, lo);
        size_t i0 = (size_t)(b * SEQ + r0) * DMODEL + h * 64 + d;
        *(uint32_t*)&s_ch[i0] = hi;
        *(uint32_t*)&s_cl[i0] = lo;
        packhl(ctxa[nt][2] * inv1, ctxa[nt][3] * inv1, hi, lo);
        size_t i1 = (size_t)(b * SEQ + r0 + 8) * DMODEL + h * 64 + d;
        *(uint32_t*)&s_ch[i1] = hi;
        *(uint32_t*)&s_cl[i1] = lo;
    }
}

// ---------------------------------------------------------------------------
extern "C" void kernel_launch(void* const* d_in, const int* in_sizes, int n_in,
                              void* d_out, int out_size)
{
    (void)in_sizes; (void)n_in; (void)out_size;
    const float* q  = (const float*)d_in[0];
    const float* k  = (const float*)d_in[1];
    const float* v  = (const float*)d_in[2];
    const float* Wq = (const float*)d_in[3];
    const float* bq = (const float*)d_in[4];
    const float* Wk = (const float*)d_in[5];
    const float* bk = (const float*)d_in[6];
    const float* Wv = (const float*)d_in[7];
    const float* bv = (const float*)d_in[8];
    const float* Wo = (const float*)d_in[9];
    const float* bo = (const float*)d_in[10];
    float* out = (float*)d_out;

    __half *qh, *ql, *kh, *kl, *vh, *vl, *ch, *cl, *w;
    __half *aqh, *aql, *ak, *avt;
    cudaGetSymbolAddress((void**)&qh, s_qh); cudaGetSymbolAddress((void**)&ql, s_ql);
    cudaGetSymbolAddress((void**)&kh, s_kh); cudaGetSymbolAddress((void**)&kl, s_kl);
    cudaGetSymbolAddress((void**)&vh, s_vh); cudaGetSymbolAddress((void**)&vl, s_vl);
    cudaGetSymbolAddress((void**)&ch, s_ch); cudaGetSymbolAddress((void**)&cl, s_cl);
    cudaGetSymbolAddress((void**)&w, s_w);
    cudaGetSymbolAddress((void**)&aqh, a_qh); cudaGetSymbolAddress((void**)&aql, a_ql);
    cudaGetSymbolAddress((void**)&ak, a_k); cudaGetSymbolAddress((void**)&avt, a_vt);

    const int GSM = 3 * GSTG;   // 120KB
    cudaFuncSetAttribute(gemm_mma<0>, cudaFuncAttributeMaxDynamicSharedMemorySize, GSM);
    cudaFuncSetAttribute(gemm_mma<1>, cudaFuncAttributeMaxDynamicSharedMemorySize, GSM);
    cudaFuncSetAttribute(gemm_mma<2>, cudaFuncAttributeMaxDynamicSharedMemorySize, GSM);
    cudaFuncSetAttribute(gemm_mma<3>, cudaFuncAttributeMaxDynamicSharedMemorySize, GSM);
    cudaFuncSetAttribute(attn_mma, cudaFuncAttributeMaxDynamicSharedMemorySize, 65536);

    const size_t WSZ = (size_t)DMODEL * DMODEL;
    const int NX4 = MROWS * DMODEL / 4;
    const int NW4 = DMODEL * DMODEL / 4;
    split_kernel<<<NX4 / 256, 256>>>(q, qh, ql, NX4);
    split_kernel<<<NX4 / 256, 256>>>(k, kh, kl, NX4);
    split_kernel<<<NX4 / 256, 256>>>(v, vh, vl, NX4);
    cvt_kernel<<<NW4 / 256, 256>>>(Wq, w + 0 * WSZ, NW4);
    cvt_kernel<<<NW4 / 256, 256>>>(Wk, w + 1 * WSZ, NW4);
    cvt_kernel<<<NW4 / 256, 256>>>(Wv, w + 2 * WSZ, NW4);
    cvt_kernel<<<NW4 / 256, 256>>>(Wo, w + 3 * WSZ, NW4);

    dim3 gg(DMODEL / 128, MROWS / 256);  // (8, 16)
    gemm_mma<1><<<gg, 256, GSM>>>(qh, ql, w + 0 * WSZ, bq, nullptr, aqh, aql);
    gemm_mma<3><<<gg, 256, GSM>>>(kh, kl, w + 1 * WSZ, bk, nullptr, ak, nullptr);
    gemm_mma<2><<<gg, 256, GSM>>>(vh, vl, w + 2 * WSZ, bv, nullptr, avt, nullptr);

    attn_mma<<<dim3(BHN, SEQ / 128), 256, 65536>>>();

    gemm_mma<0><<<gg, 256, GSM>>>(ch, cl, w + 3 * WSZ, bo, out, nullptr, nullptr);
}

// round 9
// speedup vs baseline: 1.7451x; 1.2067x over previous
#include <cuda_runtime.h>
#include <cuda_fp16.h>
#include <cstdint>
#include <math.h>

#define H 16
#define DMODEL 1024
#define DK 64
#define NB 2
#define SEQ 2048
#define MROWS (NB*SEQ)   // 4096
#define BHN (NB*H)       // 32

// ---------------- scratch (device globals; no allocation allowed) ----------
// activations split hi+lo (A-side of proj GEMMs)
__device__ __half s_qh[MROWS * DMODEL], s_ql[MROWS * DMODEL];
__device__ __half s_kh[MROWS * DMODEL], s_kl[MROWS * DMODEL];
__device__ __half s_vh[MROWS * DMODEL], s_vl[MROWS * DMODEL];
__device__ __half s_ch[MROWS * DMODEL];          // ctx single fp16
// weights single fp16 (B-side)
__device__ __half s_w[4][DMODEL * DMODEL];
// attention operands: Q split (A-side), K / V^T single fp16 (B-side)
__device__ __half a_qh[BHN * SEQ * DK], a_ql[BHN * SEQ * DK];
__device__ __half a_k[BHN * SEQ * DK];
__device__ __half a_vt[BHN * DK * SEQ];

// ---------------- helpers ---------------------------------------------------
static __device__ __forceinline__ uint32_t smem_u32(const void* p) {
    uint32_t a;
    asm("{ .reg .u64 t; cvta.to.shared.u64 t, %1; cvt.u32.u64 %0, t; }"
        : "=r"(a) : "l"(p));
    return a;
}
static __device__ __forceinline__ void cp16(uint32_t s, const void* g) {
    asm volatile("cp.async.cg.shared.global [%0], [%1], 16;" :: "r"(s), "l"(g));
}
#define CP_COMMIT() asm volatile("cp.async.commit_group;")
template <int N>
static __device__ __forceinline__ void cp_wait() {
    asm volatile("cp.async.wait_group %0;" :: "n"(N));
}
static __device__ __forceinline__ void ldm_x4(uint32_t& r0, uint32_t& r1,
                                              uint32_t& r2, uint32_t& r3, uint32_t a) {
    asm volatile("ldmatrix.sync.aligned.m8n8.x4.shared.b16 {%0,%1,%2,%3}, [%4];"
                 : "=r"(r0), "=r"(r1), "=r"(r2), "=r"(r3) : "r"(a));
}
static __device__ __forceinline__ void mma_f16(float* c, const uint32_t* a,
                                               const uint32_t* b) {
    asm volatile(
        "mma.sync.aligned.m16n8k16.row.col.f32.f16.f16.f32 "
        "{%0,%1,%2,%3}, {%4,%5,%6,%7}, {%8,%9}, {%0,%1,%2,%3};"
        : "+f"(c[0]), "+f"(c[1]), "+f"(c[2]), "+f"(c[3])
        : "r"(a[0]), "r"(a[1]), "r"(a[2]), "r"(a[3]), "r"(b[0]), "r"(b[1]));
}
static __device__ __forceinline__ float ex2(float x) {
    float y; asm("ex2.approx.f32 %0, %1;" : "=f"(y) : "f"(x)); return y;
}
// pack two floats -> fp16x2 hi and fp16x2 lo (residual)
static __device__ __forceinline__ void packhl(float a, float b,
                                              uint32_t& hi, uint32_t& lo) {
    __half ah = __float2half_rn(a), bh = __float2half_rn(b);
    __half al = __float2half_rn(a - __half2float(ah));
    __half bl = __float2half_rn(b - __half2float(bh));
    __half2 h2 = __halves2half2(ah, bh);
    __half2 l2 = __halves2half2(al, bl);
    hi = *(uint32_t*)&h2; lo = *(uint32_t*)&l2;
}
static __device__ __forceinline__ uint32_t pack2h(float a, float b) {
    __half2 h2 = __halves2half2(__float2half_rn(a), __float2half_rn(b));
    return *(uint32_t*)&h2;
}

// ---------------------------------------------------------------------------
// split fp32 -> fp16 hi + fp16 lo  (activations)
// ---------------------------------------------------------------------------
__global__ void split_kernel(const float* __restrict__ x,
                             __half* __restrict__ hi,
                             __half* __restrict__ lo, int n4)
{
    int i = blockIdx.x * 256 + threadIdx.x;
    if (i >= n4) return;
    float4 v = ((const float4*)x)[i];
    uint32_t h2[2], l2[2];
    packhl(v.x, v.y, h2[0], l2[0]);
    packhl(v.z, v.w, h2[1], l2[1]);
    ((uint32_t*)hi)[2 * i] = h2[0];
    ((uint32_t*)hi)[2 * i + 1] = h2[1];
    ((uint32_t*)lo)[2 * i] = l2[0];
    ((uint32_t*)lo)[2 * i + 1] = l2[1];
}
// convert fp32 -> single fp16  (weights)
__global__ void cvt_kernel(const float* __restrict__ x,
                           __half* __restrict__ yh, int n4)
{
    int i = blockIdx.x * 256 + threadIdx.x;
    if (i >= n4) return;
    float4 v = ((const float4*)x)[i];
    ((uint32_t*)yh)[2 * i] = pack2h(v.x, v.y);
    ((uint32_t*)yh)[2 * i + 1] = pack2h(v.z, v.w);
}

// ---------------------------------------------------------------------------
// fp16 GEMM: Y = (Ah [+ Al]) @ B^T + bias.  256x128 CTA tile (4m x 2n warps,
// warp 64x64), BK=32.  Stage (40KB): Ah 16K | Al 16K | B 8K.
// NPASS = 1 or 2 (A-side split passes).  3-stage cp.async pipeline.
// Epilogue modes: 0 fp32 flat | 1 head hi+lo | 2 transposed hi | 3 head hi.
// ---------------------------------------------------------------------------
#define NIT2 32      // 1024 / 32
#define GSTG 40960   // 40KB per stage

template <int MODE, int NPASS>
__global__ void __launch_bounds__(256, 1)
gemm_mma(const __half* __restrict__ Ah, const __half* __restrict__ Al,
         const __half* __restrict__ B,
         const float* __restrict__ bias, float* __restrict__ Y,
         __half* __restrict__ Yh, __half* __restrict__ Yl)
{
    extern __shared__ __align__(128) char dsm[];
    const uint32_t sS = smem_u32(dsm);     // 3 stages x 40KB

    const int tid = threadIdx.x;
    const int wid = tid >> 5, lane = tid & 31;
    const int wm = wid >> 1, wn = wid & 1;      // 4m x 2n
    const int m0 = blockIdx.y << 8, n0 = blockIdx.x << 7;

    float acc[4][8][4];
#pragma unroll
    for (int i = 0; i < 4; i++)
#pragma unroll
        for (int j = 0; j < 8; j++)
#pragma unroll
            for (int u = 0; u < 4; u++) acc[i][j][u] = 0.0f;

    const int lc = tid & 3;                 // 16B chunk within 64B row

    auto load_it = [&](int it2, int st) {
        const int kk = it2 << 5;            // k offset (fp16 elems)
        uint32_t b = sS + (uint32_t)st * GSTG;
#pragma unroll
        for (int j = 0; j < 4; j++) {
            int cid = tid + 256 * j;        // 0..1023
            int row = cid >> 2;             // 0..255
            uint32_t off = (uint32_t)(row * 64 + ((lc ^ (row & 3)) << 4));
            size_t ga = (size_t)(m0 + row) * DMODEL + kk + lc * 8;
            cp16(b + off, Ah + ga);
            if (NPASS == 2) cp16(b + 16384u + off, Al + ga);
        }
#pragma unroll
        for (int j = 0; j < 2; j++) {
            int cid = tid + 256 * j;        // 0..511
            int row = cid >> 2;             // 0..127
            uint32_t off = (uint32_t)(row * 64 + ((lc ^ (row & 3)) << 4));
            size_t gb = (size_t)(n0 + row) * DMODEL + kk + lc * 8;
            cp16(b + 32768u + off, B + gb);
        }
        CP_COMMIT();
    };

    const int arow = wm * 64 + (lane & 15);
    const int abit = lane >> 4;
    const int brow = wn * 64 + (lane & 7) + ((lane >> 4) & 1) * 8;
    const int bbit = (lane >> 3) & 1;

    load_it(0, 0);
    load_it(1, 1);

    int st = 0;
    for (int it = 0; it < NIT2; ++it) {
        if (it + 1 < NIT2) cp_wait<1>(); else cp_wait<0>();
        __syncthreads();
        if (it + 2 < NIT2) {
            int st2 = st + 2; if (st2 >= 3) st2 -= 3;
            load_it(it + 2, st2);
        }

        const uint32_t sb = sS + (uint32_t)st * GSTG;

#pragma unroll
        for (int ks = 0; ks < 2; ks++) {
            uint32_t bh4[4][4];
#pragma unroll
            for (int np = 0; np < 4; np++) {
                int row = brow + np * 16;
                int ch = 2 * ks + bbit;
                uint32_t off = (uint32_t)(row * 64 + ((ch ^ (row & 3)) << 4));
                ldm_x4(bh4[np][0], bh4[np][1], bh4[np][2], bh4[np][3], sb + 32768u + off);
            }
            uint32_t af[4][4];
#pragma unroll
            for (int mt = 0; mt < 4; mt++) {
                int row = arow + mt * 16;
                int ch = 2 * ks + abit;
                uint32_t ad = sb + (uint32_t)(row * 64 + ((ch ^ (row & 3)) << 4));
                ldm_x4(af[mt][0], af[mt][1], af[mt][2], af[mt][3], ad);
            }
#pragma unroll
            for (int mt = 0; mt < 4; mt++)
#pragma unroll
                for (int nn = 0; nn < 8; nn++)
                    mma_f16(acc[mt][nn], af[mt], bh4[nn >> 1] + (nn & 1) * 2);
            if (NPASS == 2) {
#pragma unroll
                for (int mt = 0; mt < 4; mt++) {
                    int row = arow + mt * 16;
                    int ch = 2 * ks + abit;
                    uint32_t ad = sb + 16384u + (uint32_t)(row * 64 + ((ch ^ (row & 3)) << 4));
                    ldm_x4(af[mt][0], af[mt][1], af[mt][2], af[mt][3], ad);
                }
#pragma unroll
                for (int mt = 0; mt < 4; mt++)
#pragma unroll
                    for (int nn = 0; nn < 8; nn++)
                        mma_f16(acc[mt][nn], af[mt], bh4[nn >> 1] + (nn & 1) * 2);
            }
        }
        if (++st == 3) st = 0;
    }

    // ---- epilogue ----
    const int ml = lane >> 2;
    const int nl = (lane & 3) << 1;
#pragma unroll
    for (int mt = 0; mt < 4; mt++) {
#pragma unroll
        for (int half = 0; half < 2; half++) {
            int m = m0 + wm * 64 + mt * 16 + ml + half * 8;
#pragma unroll
            for (int nn = 0; nn < 8; nn++) {
                int n = n0 + wn * 64 + nn * 8 + nl;
                float x = acc[mt][nn][2 * half + 0] + bias[n + 0];
                float y = acc[mt][nn][2 * half + 1] + bias[n + 1];
                if (MODE == 0) {
                    float2 o; o.x = x; o.y = y;
                    *(float2*)&Y[(size_t)m * DMODEL + n] = o;
                } else {
                    int bb = m >> 11, s = m & 2047;
                    int h = n >> 6, d = n & 63;
                    if (MODE == 1) {
                        uint32_t hi, lo;
                        packhl(x, y, hi, lo);
                        size_t idx = (size_t)((bb * H + h) * SEQ + s) * DK + d;
                        *(uint32_t*)&Yh[idx] = hi;
                        *(uint32_t*)&Yl[idx] = lo;
                    } else if (MODE == 3) {
                        size_t idx = (size_t)((bb * H + h) * SEQ + s) * DK + d;
                        *(uint32_t*)&Yh[idx] = pack2h(x, y);
                    } else {
                        size_t base = (size_t)((bb * H + h) * DK + d) * SEQ + s;
                        Yh[base] = __float2half_rn(x);
                        Yh[base + SEQ] = __float2half_rn(y);
                    }
                }
            }
        }
    }
}

// ---------------------------------------------------------------------------
// fp16 flash attention.  BQ=128, BKV=64, 8 warps x 16 q-rows.
// Q split (hi+lo frags resident); K / V^T single fp16, double-buffered.
// S = (Qh+Ql)*K (2 passes); ctx += P*V (P single fp16, 1 pass).
// Smem: Qh 16K | Ql 16K | 2 x (K 8K | V 8K) = 64KB.
// ---------------------------------------------------------------------------
__global__ void __launch_bounds__(256)
attn_mma()
{
    extern __shared__ __align__(128) char dsm[];
    const uint32_t sbase = smem_u32(dsm);
    const uint32_t sQh = sbase, sQl = sbase + 16384;
    const uint32_t sKV = sbase + 32768;           // + buf*16384

    const int bh = blockIdx.x;
    const int q0 = blockIdx.y << 7;
    const int tid = threadIdx.x, wid = tid >> 5, lane = tid & 31;

    const __half* qhg = a_qh + (size_t)bh * SEQ * DK;
    const __half* qlg = a_ql + (size_t)bh * SEQ * DK;
    const __half* kg = a_k + (size_t)bh * SEQ * DK;
    const __half* vg = a_vt + (size_t)bh * DK * SEQ;

#pragma unroll
    for (int j = 0; j < 4; j++) {
        int cid = tid + 256 * j;
        int hr = cid >> 2, c = cid & 3;
        int qrow = hr & 127, panel = hr >> 7;
        uint32_t off = (uint32_t)(hr * 64 + ((c ^ (hr & 3)) << 4));
        const size_t src = (size_t)(q0 + qrow) * DK + panel * 32 + c * 8;
        cp16(sQh + off, qhg + src);
        cp16(sQl + off, qlg + src);
    }
    CP_COMMIT();
    cp_wait<0>();
    __syncthreads();

    uint32_t fQh[4][4], fQl[4][4];
    {
        const int row = wid * 16 + (lane & 15);
#pragma unroll
        for (int kf = 0; kf < 4; kf++) {
            int ch = ((kf & 1) << 1) + (lane >> 4);
            uint32_t off = (uint32_t)((kf >> 1) * 8192 + row * 64 + ((ch ^ (row & 3)) << 4));
            ldm_x4(fQh[kf][0], fQh[kf][1], fQh[kf][2], fQh[kf][3], sQh + off);
            ldm_x4(fQl[kf][0], fQl[kf][1], fQl[kf][2], fQl[kf][3], sQl + off);
        }
    }

    float ctxa[8][4];
#pragma unroll
    for (int i = 0; i < 8; i++)
#pragma unroll
        for (int u = 0; u < 4; u++) ctxa[i][u] = 0.0f;
    float mrun[2] = {-1e30f, -1e30f};
    float lrun[2] = {0.0f, 0.0f};

    auto load_kv = [&](int kt, int buf) {
        uint32_t base = sKV + buf * 16384;
#pragma unroll
        for (int j = 0; j < 2; j++) {
            int cid = tid + 256 * j;
            int hr = cid >> 2, c = cid & 3;
            uint32_t off = (uint32_t)(hr * 64 + ((c ^ (hr & 3)) << 4));
            int lo6 = hr & 63, pan = hr >> 6;
            size_t ksrc = (size_t)(kt + lo6) * DK + pan * 32 + c * 8;
            size_t vsrc = (size_t)lo6 * SEQ + kt + pan * 32 + c * 8;
            cp16(base + off, kg + ksrc);
            cp16(base + 8192 + off, vg + vsrc);
        }
        CP_COMMIT();
    };

    const int brow = (lane & 7) + ((lane >> 4) & 1) * 8;
    const int bbit = (lane >> 3) & 1;
    const float C2 = 0.18033688f;   // log2(e)/8

    load_kv(0, 0);

    for (int t = 0; t < SEQ / 64; ++t) {
        if (t + 1 < SEQ / 64) { load_kv((t + 1) * 64, (t + 1) & 1); cp_wait<1>(); }
        else cp_wait<0>();
        __syncthreads();

        const uint32_t base = sKV + (t & 1) * 16384;

        // ---- S = (Qh + Ql) * K ----
        float sacc[8][4];
#pragma unroll
        for (int i = 0; i < 8; i++)
#pragma unroll
            for (int u = 0; u < 4; u++) sacc[i][u] = 0.0f;

#pragma unroll
        for (int kf = 0; kf < 4; kf++) {
#pragma unroll
            for (int np = 0; np < 4; np++) {
                int row = np * 16 + brow;
                int ch = ((kf & 1) << 1) + bbit;
                uint32_t off = (uint32_t)((kf >> 1) * 4096 + row * 64 + ((ch ^ (row & 3)) << 4));
                uint32_t kh4[4];
                ldm_x4(kh4[0], kh4[1], kh4[2], kh4[3], base + off);
                mma_f16(sacc[2 * np], fQh[kf], kh4 + 0);
                mma_f16(sacc[2 * np + 1], fQh[kf], kh4 + 2);
                mma_f16(sacc[2 * np], fQl[kf], kh4 + 0);
                mma_f16(sacc[2 * np + 1], fQl[kf], kh4 + 2);
            }
        }

        // ---- online softmax (base-2) ----
        float rmax0 = -1e30f, rmax1 = -1e30f;
#pragma unroll
        for (int i = 0; i < 8; i++) {
            rmax0 = fmaxf(rmax0, fmaxf(sacc[i][0], sacc[i][1]));
            rmax1 = fmaxf(rmax1, fmaxf(sacc[i][2], sacc[i][3]));
        }
        rmax0 = fmaxf(rmax0, __shfl_xor_sync(0xffffffffu, rmax0, 1));
        rmax0 = fmaxf(rmax0, __shfl_xor_sync(0xffffffffu, rmax0, 2));
        rmax1 = fmaxf(rmax1, __shfl_xor_sync(0xffffffffu, rmax1, 1));
        rmax1 = fmaxf(rmax1, __shfl_xor_sync(0xffffffffu, rmax1, 2));
        float mn0 = fmaxf(mrun[0], C2 * rmax0);
        float mn1 = fmaxf(mrun[1], C2 * rmax1);
        float al0 = ex2(mrun[0] - mn0);
        float al1 = ex2(mrun[1] - mn1);
        mrun[0] = mn0; mrun[1] = mn1;
#pragma unroll
        for (int i = 0; i < 8; i++) {
            ctxa[i][0] *= al0; ctxa[i][1] *= al0;
            ctxa[i][2] *= al1; ctxa[i][3] *= al1;
        }
        float rs0 = 0.0f, rs1 = 0.0f;
#pragma unroll
        for (int i = 0; i < 8; i++) {
            sacc[i][0] = ex2(fmaf(C2, sacc[i][0], -mn0));
            sacc[i][1] = ex2(fmaf(C2, sacc[i][1], -mn0));
            sacc[i][2] = ex2(fmaf(C2, sacc[i][2], -mn1));
            sacc[i][3] = ex2(fmaf(C2, sacc[i][3], -mn1));
            rs0 += sacc[i][0] + sacc[i][1];
            rs1 += sacc[i][2] + sacc[i][3];
        }
        rs0 += __shfl_xor_sync(0xffffffffu, rs0, 1);
        rs0 += __shfl_xor_sync(0xffffffffu, rs0, 2);
        rs1 += __shfl_xor_sync(0xffffffffu, rs1, 1);
        rs1 += __shfl_xor_sync(0xffffffffu, rs1, 2);
        lrun[0] = lrun[0] * al0 + rs0;
        lrun[1] = lrun[1] * al1 + rs1;

        // ---- ctx += P * V  (P single fp16) ----
#pragma unroll
        for (int kf = 0; kf < 4; kf++) {
            uint32_t pH[4];
            pH[0] = pack2h(sacc[2 * kf][0], sacc[2 * kf][1]);
            pH[1] = pack2h(sacc[2 * kf][2], sacc[2 * kf][3]);
            pH[2] = pack2h(sacc[2 * kf + 1][0], sacc[2 * kf + 1][1]);
            pH[3] = pack2h(sacc[2 * kf + 1][2], sacc[2 * kf + 1][3]);
#pragma unroll
            for (int np = 0; np < 4; np++) {
                int row = np * 16 + brow;
                int ch = ((kf & 1) << 1) + bbit;
                uint32_t off = (uint32_t)((kf >> 1) * 4096 + row * 64 + ((ch ^ (row & 3)) << 4));
                uint32_t vh4[4];
                ldm_x4(vh4[0], vh4[1], vh4[2], vh4[3], base + 8192 + off);
                mma_f16(ctxa[2 * np], pH, vh4 + 0);
                mma_f16(ctxa[2 * np + 1], pH, vh4 + 2);
            }
        }
        __syncthreads();
    }

    // ---- epilogue: ctx/l -> single fp16, flat [b*S+s][h*64+d] ----
    const float inv0 = 1.0f / lrun[0];
    const float inv1 = 1.0f / lrun[1];
    const int b = bh >> 4, h = bh & 15;
    const int r0 = q0 + wid * 16 + (lane >> 2);
    const int nl = (lane & 3) << 1;
#pragma unroll
    for (int nt = 0; nt < 8; nt++) {
        int d = nt * 8 + nl;
        size_t i0 = (size_t)(b * SEQ + r0) * DMODEL + h * 64 + d;
        *(uint32_t*)&s_ch[i0] = pack2h(ctxa[nt][0] * inv0, ctxa[nt][1] * inv0);
        size_t i1 = (size_t)(b * SEQ + r0 + 8) * DMODEL + h * 64 + d;
        *(uint32_t*)&s_ch[i1] = pack2h(ctxa[nt][2] * inv1, ctxa[nt][3] * inv1);
    }
}

// ---------------------------------------------------------------------------
extern "C" void kernel_launch(void* const* d_in, const int* in_sizes, int n_in,
                              void* d_out, int out_size)
{
    (void)in_sizes; (void)n_in; (void)out_size;
    const float* q  = (const float*)d_in[0];
    const float* k  = (const float*)d_in[1];
    const float* v  = (const float*)d_in[2];
    const float* Wq = (const float*)d_in[3];
    const float* bq = (const float*)d_in[4];
    const float* Wk = (const float*)d_in[5];
    const float* bk = (const float*)d_in[6];
    const float* Wv = (const float*)d_in[7];
    const float* bv = (const float*)d_in[8];
    const float* Wo = (const float*)d_in[9];
    const float* bo = (const float*)d_in[10];
    float* out = (float*)d_out;

    __half *qh, *ql, *kh, *kl, *vh, *vl, *ch, *w;
    __half *aqh, *aql, *ak, *avt;
    cudaGetSymbolAddress((void**)&qh, s_qh); cudaGetSymbolAddress((void**)&ql, s_ql);
    cudaGetSymbolAddress((void**)&kh, s_kh); cudaGetSymbolAddress((void**)&kl, s_kl);
    cudaGetSymbolAddress((void**)&vh, s_vh); cudaGetSymbolAddress((void**)&vl, s_vl);
    cudaGetSymbolAddress((void**)&ch, s_ch);
    cudaGetSymbolAddress((void**)&w, s_w);
    cudaGetSymbolAddress((void**)&aqh, a_qh); cudaGetSymbolAddress((void**)&aql, a_ql);
    cudaGetSymbolAddress((void**)&ak, a_k); cudaGetSymbolAddress((void**)&avt, a_vt);

    const int GSM = 3 * GSTG;   // 120KB
    cudaFuncSetAttribute((const void*)gemm_mma<0,1>, cudaFuncAttributeMaxDynamicSharedMemorySize, GSM);
    cudaFuncSetAttribute((const void*)gemm_mma<1,2>, cudaFuncAttributeMaxDynamicSharedMemorySize, GSM);
    cudaFuncSetAttribute((const void*)gemm_mma<2,2>, cudaFuncAttributeMaxDynamicSharedMemorySize, GSM);
    cudaFuncSetAttribute((const void*)gemm_mma<3,2>, cudaFuncAttributeMaxDynamicSharedMemorySize, GSM);
    cudaFuncSetAttribute(attn_mma, cudaFuncAttributeMaxDynamicSharedMemorySize, 65536);

    const size_t WSZ = (size_t)DMODEL * DMODEL;
    const int NX4 = MROWS * DMODEL / 4;
    const int NW4 = DMODEL * DMODEL / 4;
    split_kernel<<<NX4 / 256, 256>>>(q, qh, ql, NX4);
    split_kernel<<<NX4 / 256, 256>>>(k, kh, kl, NX4);
    split_kernel<<<NX4 / 256, 256>>>(v, vh, vl, NX4);
    cvt_kernel<<<NW4 / 256, 256>>>(Wq, w + 0 * WSZ, NW4);
    cvt_kernel<<<NW4 / 256, 256>>>(Wk, w + 1 * WSZ, NW4);
    cvt_kernel<<<NW4 / 256, 256>>>(Wv, w + 2 * WSZ, NW4);
    cvt_kernel<<<NW4 / 256, 256>>>(Wo, w + 3 * WSZ, NW4);

    dim3 gg(DMODEL / 128, MROWS / 256);  // (8, 16)
    gemm_mma<1,2><<<gg, 256, GSM>>>(qh, ql, w + 0 * WSZ, bq, nullptr, aqh, aql);
    gemm_mma<3,2><<<gg, 256, GSM>>>(kh, kl, w + 1 * WSZ, bk, nullptr, ak, nullptr);
    gemm_mma<2,2><<<gg, 256, GSM>>>(vh, vl, w + 2 * WSZ, bv, nullptr, avt, nullptr);

    attn_mma<<<dim3(BHN, SEQ / 128), 256, 65536>>>();

    gemm_mma<0,1><<<gg, 256, GSM>>>(ch, nullptr, w + 3 * WSZ, bo, out, nullptr, nullptr);
}

// round 10
// speedup vs baseline: 2.0820x; 1.1931x over previous
#include <cuda_runtime.h>
#include <cuda_fp16.h>
#include <cstdint>
#include <math.h>

#define H 16
#define DMODEL 1024
#define DK 64
#define NB 2
#define SEQ 2048
#define MROWS (NB*SEQ)   // 4096
#define BHN (NB*H)       // 32

// ---------------- scratch (device globals; no allocation allowed) ----------
__device__ __half s_xq[MROWS * DMODEL];   // inputs converted to fp16
__device__ __half s_xk[MROWS * DMODEL];
__device__ __half s_xv[MROWS * DMODEL];
__device__ __half s_c16[MROWS * DMODEL];  // ctx fp16
__device__ __half s_w[4][DMODEL * DMODEL];
// attention operands (head layout / transposed), single fp16
__device__ __half a_q[BHN * SEQ * DK];
__device__ __half a_k[BHN * SEQ * DK];
__device__ __half a_vt[BHN * DK * SEQ];

// ---------------- helpers ---------------------------------------------------
static __device__ __forceinline__ uint32_t smem_u32(const void* p) {
    uint32_t a;
    asm("{ .reg .u64 t; cvta.to.shared.u64 t, %1; cvt.u32.u64 %0, t; }"
        : "=r"(a) : "l"(p));
    return a;
}
static __device__ __forceinline__ void cp16(uint32_t s, const void* g) {
    asm volatile("cp.async.cg.shared.global [%0], [%1], 16;" :: "r"(s), "l"(g));
}
#define CP_COMMIT() asm volatile("cp.async.commit_group;")
template <int N>
static __device__ __forceinline__ void cp_wait() {
    asm volatile("cp.async.wait_group %0;" :: "n"(N));
}
static __device__ __forceinline__ void ldm_x4(uint32_t& r0, uint32_t& r1,
                                              uint32_t& r2, uint32_t& r3, uint32_t a) {
    asm volatile("ldmatrix.sync.aligned.m8n8.x4.shared.b16 {%0,%1,%2,%3}, [%4];"
                 : "=r"(r0), "=r"(r1), "=r"(r2), "=r"(r3) : "r"(a));
}
static __device__ __forceinline__ void mma_f16(float* c, const uint32_t* a,
                                               const uint32_t* b) {
    asm volatile(
        "mma.sync.aligned.m16n8k16.row.col.f32.f16.f16.f32 "
        "{%0,%1,%2,%3}, {%4,%5,%6,%7}, {%8,%9}, {%0,%1,%2,%3};"
        : "+f"(c[0]), "+f"(c[1]), "+f"(c[2]), "+f"(c[3])
        : "r"(a[0]), "r"(a[1]), "r"(a[2]), "r"(a[3]), "r"(b[0]), "r"(b[1]));
}
static __device__ __forceinline__ float ex2(float x) {
    float y; asm("ex2.approx.f32 %0, %1;" : "=f"(y) : "f"(x)); return y;
}
static __device__ __forceinline__ uint32_t pack2h(float a, float b) {
    __half2 h2 = __halves2half2(__float2half_rn(a), __float2half_rn(b));
    return *(uint32_t*)&h2;
}

// ---------------------------------------------------------------------------
// convert fp32 -> fp16
// ---------------------------------------------------------------------------
__global__ void cvt_kernel(const float* __restrict__ x,
                           __half* __restrict__ yh, int n4)
{
    int i = blockIdx.x * 256 + threadIdx.x;
    if (i >= n4) return;
    float4 v = ((const float4*)x)[i];
    ((uint32_t*)yh)[2 * i] = pack2h(v.x, v.y);
    ((uint32_t*)yh)[2 * i + 1] = pack2h(v.z, v.w);
}

// ---------------------------------------------------------------------------
// fp16 single-pass GEMM: Y = A @ B^T + bias.  256x128 CTA tile (4m x 2n
// warps, warp 64x64), BK=32.  Stage (24KB): A 16K | B 8K.  3-stage cp.async
// pipeline.  Epilogue modes: 0 fp32 flat | 2 transposed fp16 | 3 head fp16.
// ---------------------------------------------------------------------------
#define NIT2 32      // 1024 / 32
#define GSTG 24576   // 24KB per stage

template <int MODE>
__global__ void __launch_bounds__(256, 1)
gemm_mma(const __half* __restrict__ A, const __half* __restrict__ B,
         const float* __restrict__ bias, float* __restrict__ Y,
         __half* __restrict__ Yh)
{
    extern __shared__ __align__(128) char dsm[];
    const uint32_t sS = smem_u32(dsm);     // 3 stages x 24KB

    const int tid = threadIdx.x;
    const int wid = tid >> 5, lane = tid & 31;
    const int wm = wid >> 1, wn = wid & 1;      // 4m x 2n
    const int m0 = blockIdx.y << 8, n0 = blockIdx.x << 7;

    float acc[4][8][4];
#pragma unroll
    for (int i = 0; i < 4; i++)
#pragma unroll
        for (int j = 0; j < 8; j++)
#pragma unroll
            for (int u = 0; u < 4; u++) acc[i][j][u] = 0.0f;

    const int lc = tid & 3;                 // 16B chunk within 64B row

    auto load_it = [&](int it2, int st) {
        const int kk = it2 << 5;            // k offset (fp16 elems)
        uint32_t b = sS + (uint32_t)st * GSTG;
#pragma unroll
        for (int j = 0; j < 4; j++) {
            int cid = tid + 256 * j;        // 0..1023
            int row = cid >> 2;             // 0..255
            uint32_t off = (uint32_t)(row * 64 + ((lc ^ (row & 3)) << 4));
            size_t ga = (size_t)(m0 + row) * DMODEL + kk + lc * 8;
            cp16(b + off, A + ga);
        }
#pragma unroll
        for (int j = 0; j < 2; j++) {
            int cid = tid + 256 * j;        // 0..511
            int row = cid >> 2;             // 0..127
            uint32_t off = (uint32_t)(row * 64 + ((lc ^ (row & 3)) << 4));
            size_t gb = (size_t)(n0 + row) * DMODEL + kk + lc * 8;
            cp16(b + 16384u + off, B + gb);
        }
        CP_COMMIT();
    };

    const int arow = wm * 64 + (lane & 15);
    const int abit = lane >> 4;
    const int brow = wn * 64 + (lane & 7) + ((lane >> 4) & 1) * 8;
    const int bbit = (lane >> 3) & 1;

    load_it(0, 0);
    load_it(1, 1);

    int st = 0;
    for (int it = 0; it < NIT2; ++it) {
        if (it + 1 < NIT2) cp_wait<1>(); else cp_wait<0>();
        __syncthreads();
        if (it + 2 < NIT2) {
            int st2 = st + 2; if (st2 >= 3) st2 -= 3;
            load_it(it + 2, st2);
        }

        const uint32_t sb = sS + (uint32_t)st * GSTG;

#pragma unroll
        for (int ks = 0; ks < 2; ks++) {
            uint32_t bh4[4][4];
#pragma unroll
            for (int np = 0; np < 4; np++) {
                int row = brow + np * 16;
                int ch = 2 * ks + bbit;
                uint32_t off = (uint32_t)(row * 64 + ((ch ^ (row & 3)) << 4));
                ldm_x4(bh4[np][0], bh4[np][1], bh4[np][2], bh4[np][3], sb + 16384u + off);
            }
            uint32_t af[4][4];
#pragma unroll
            for (int mt = 0; mt < 4; mt++) {
                int row = arow + mt * 16;
                int ch = 2 * ks + abit;
                uint32_t ad = sb + (uint32_t)(row * 64 + ((ch ^ (row & 3)) << 4));
                ldm_x4(af[mt][0], af[mt][1], af[mt][2], af[mt][3], ad);
            }
#pragma unroll
            for (int mt = 0; mt < 4; mt++)
#pragma unroll
                for (int nn = 0; nn < 8; nn++)
                    mma_f16(acc[mt][nn], af[mt], bh4[nn >> 1] + (nn & 1) * 2);
        }
        if (++st == 3) st = 0;
    }

    // ---- epilogue ----
    const int ml = lane >> 2;
    const int nl = (lane & 3) << 1;
#pragma unroll
    for (int mt = 0; mt < 4; mt++) {
#pragma unroll
        for (int half = 0; half < 2; half++) {
            int m = m0 + wm * 64 + mt * 16 + ml + half * 8;
#pragma unroll
            for (int nn = 0; nn < 8; nn++) {
                int n = n0 + wn * 64 + nn * 8 + nl;
                float x = acc[mt][nn][2 * half + 0] + bias[n + 0];
                float y = acc[mt][nn][2 * half + 1] + bias[n + 1];
                if (MODE == 0) {
                    float2 o; o.x = x; o.y = y;
                    *(float2*)&Y[(size_t)m * DMODEL + n] = o;
                } else {
                    int bb = m >> 11, s = m & 2047;
                    int h = n >> 6, d = n & 63;
                    if (MODE == 3) {
                        size_t idx = (size_t)((bb * H + h) * SEQ + s) * DK + d;
                        *(uint32_t*)&Yh[idx] = pack2h(x, y);
                    } else {
                        size_t base = (size_t)((bb * H + h) * DK + d) * SEQ + s;
                        Yh[base] = __float2half_rn(x);
                        Yh[base + SEQ] = __float2half_rn(y);
                    }
                }
            }
        }
    }
}

// ---------------------------------------------------------------------------
// fp16 single-pass flash attention.  BQ=128, BKV=64, 8 warps x 16 q-rows.
// Q frags resident; K / V^T fp16, double-buffered.  S = Q*K; ctx += P*V.
// Smem: Q 16K | 2 x (K 8K | V 8K) = 48KB.
// ---------------------------------------------------------------------------
__global__ void __launch_bounds__(256)
attn_mma()
{
    extern __shared__ __align__(128) char dsm[];
    const uint32_t sbase = smem_u32(dsm);
    const uint32_t sQ = sbase;
    const uint32_t sKV = sbase + 16384;           // + buf*16384

    const int bh = blockIdx.x;
    const int q0 = blockIdx.y << 7;
    const int tid = threadIdx.x, wid = tid >> 5, lane = tid & 31;

    const __half* qg = a_q + (size_t)bh * SEQ * DK;
    const __half* kg = a_k + (size_t)bh * SEQ * DK;
    const __half* vg = a_vt + (size_t)bh * DK * SEQ;

#pragma unroll
    for (int j = 0; j < 4; j++) {
        int cid = tid + 256 * j;
        int hr = cid >> 2, c = cid & 3;
        int qrow = hr & 127, panel = hr >> 7;
        uint32_t off = (uint32_t)(hr * 64 + ((c ^ (hr & 3)) << 4));
        const size_t src = (size_t)(q0 + qrow) * DK + panel * 32 + c * 8;
        cp16(sQ + off, qg + src);
    }
    CP_COMMIT();
    cp_wait<0>();
    __syncthreads();

    uint32_t fQ[4][4];
    {
        const int row = wid * 16 + (lane & 15);
#pragma unroll
        for (int kf = 0; kf < 4; kf++) {
            int ch = ((kf & 1) << 1) + (lane >> 4);
            uint32_t off = (uint32_t)((kf >> 1) * 8192 + row * 64 + ((ch ^ (row & 3)) << 4));
            ldm_x4(fQ[kf][0], fQ[kf][1], fQ[kf][2], fQ[kf][3], sQ + off);
        }
    }

    float ctxa[8][4];
#pragma unroll
    for (int i = 0; i < 8; i++)
#pragma unroll
        for (int u = 0; u < 4; u++) ctxa[i][u] = 0.0f;
    float mrun[2] = {-1e30f, -1e30f};
    float lrun[2] = {0.0f, 0.0f};

    auto load_kv = [&](int kt, int buf) {
        uint32_t base = sKV + buf * 16384;
#pragma unroll
        for (int j = 0; j < 2; j++) {
            int cid = tid + 256 * j;
            int hr = cid >> 2, c = cid & 3;
            uint32_t off = (uint32_t)(hr * 64 + ((c ^ (hr & 3)) << 4));
            int lo6 = hr & 63, pan = hr >> 6;
            size_t ksrc = (size_t)(kt + lo6) * DK + pan * 32 + c * 8;
            size_t vsrc = (size_t)lo6 * SEQ + kt + pan * 32 + c * 8;
            cp16(base + off, kg + ksrc);
            cp16(base + 8192 + off, vg + vsrc);
        }
        CP_COMMIT();
    };

    const int brow = (lane & 7) + ((lane >> 4) & 1) * 8;
    const int bbit = (lane >> 3) & 1;
    const float C2 = 0.18033688f;   // log2(e)/8

    load_kv(0, 0);

    for (int t = 0; t < SEQ / 64; ++t) {
        if (t + 1 < SEQ / 64) { load_kv((t + 1) * 64, (t + 1) & 1); cp_wait<1>(); }
        else cp_wait<0>();
        __syncthreads();

        const uint32_t base = sKV + (t & 1) * 16384;

        // ---- S = Q * K ----
        float sacc[8][4];
#pragma unroll
        for (int i = 0; i < 8; i++)
#pragma unroll
            for (int u = 0; u < 4; u++) sacc[i][u] = 0.0f;

#pragma unroll
        for (int kf = 0; kf < 4; kf++) {
#pragma unroll
            for (int np = 0; np < 4; np++) {
                int row = np * 16 + brow;
                int ch = ((kf & 1) << 1) + bbit;
                uint32_t off = (uint32_t)((kf >> 1) * 4096 + row * 64 + ((ch ^ (row & 3)) << 4));
                uint32_t kh4[4];
                ldm_x4(kh4[0], kh4[1], kh4[2], kh4[3], base + off);
                mma_f16(sacc[2 * np], fQ[kf], kh4 + 0);
                mma_f16(sacc[2 * np + 1], fQ[kf], kh4 + 2);
            }
        }

        // ---- online softmax (base-2) ----
        float rmax0 = -1e30f, rmax1 = -1e30f;
#pragma unroll
        for (int i = 0; i < 8; i++) {
            rmax0 = fmaxf(rmax0, fmaxf(sacc[i][0], sacc[i][1]));
            rmax1 = fmaxf(rmax1, fmaxf(sacc[i][2], sacc[i][3]));
        }
        rmax0 = fmaxf(rmax0, __shfl_xor_sync(0xffffffffu, rmax0, 1));
        rmax0 = fmaxf(rmax0, __shfl_xor_sync(0xffffffffu, rmax0, 2));
        rmax1 = fmaxf(rmax1, __shfl_xor_sync(0xffffffffu, rmax1, 1));
        rmax1 = fmaxf(rmax1, __shfl_xor_sync(0xffffffffu, rmax1, 2));
        float mn0 = fmaxf(mrun[0], C2 * rmax0);
        float mn1 = fmaxf(mrun[1], C2 * rmax1);
        float al0 = ex2(mrun[0] - mn0);
        float al1 = ex2(mrun[1] - mn1);
        mrun[0] = mn0; mrun[1] = mn1;
#pragma unroll
        for (int i = 0; i < 8; i++) {
            ctxa[i][0] *= al0; ctxa[i][1] *= al0;
            ctxa[i][2] *= al1; ctxa[i][3] *= al1;
        }
        float rs0 = 0.0f, rs1 = 0.0f;
#pragma unroll
        for (int i = 0; i < 8; i++) {
            sacc[i][0] = ex2(fmaf(C2, sacc[i][0], -mn0));
            sacc[i][1] = ex2(fmaf(C2, sacc[i][1], -mn0));
            sacc[i][2] = ex2(fmaf(C2, sacc[i][2], -mn1));
            sacc[i][3] = ex2(fmaf(C2, sacc[i][3], -mn1));
            rs0 += sacc[i][0] + sacc[i][1];
            rs1 += sacc[i][2] + sacc[i][3];
        }
        rs0 += __shfl_xor_sync(0xffffffffu, rs0, 1);
        rs0 += __shfl_xor_sync(0xffffffffu, rs0, 2);
        rs1 += __shfl_xor_sync(0xffffffffu, rs1, 1);
        rs1 += __shfl_xor_sync(0xffffffffu, rs1, 2);
        lrun[0] = lrun[0] * al0 + rs0;
        lrun[1] = lrun[1] * al1 + rs1;

        // ---- ctx += P * V ----
#pragma unroll
        for (int kf = 0; kf < 4; kf++) {
            uint32_t pH[4];
            pH[0] = pack2h(sacc[2 * kf][0], sacc[2 * kf][1]);
            pH[1] = pack2h(sacc[2 * kf][2], sacc[2 * kf][3]);
            pH[2] = pack2h(sacc[2 * kf + 1][0], sacc[2 * kf + 1][1]);
            pH[3] = pack2h(sacc[2 * kf + 1][2], sacc[2 * kf + 1][3]);
#pragma unroll
            for (int np = 0; np < 4; np++) {
                int row = np * 16 + brow;
                int ch = ((kf & 1) << 1) + bbit;
                uint32_t off = (uint32_t)((kf >> 1) * 4096 + row * 64 + ((ch ^ (row & 3)) << 4));
                uint32_t vh4[4];
                ldm_x4(vh4[0], vh4[1], vh4[2], vh4[3], base + 8192 + off);
                mma_f16(ctxa[2 * np], pH, vh4 + 0);
                mma_f16(ctxa[2 * np + 1], pH, vh4 + 2);
            }
        }
        __syncthreads();
    }

    // ---- epilogue: ctx/l -> fp16, flat [b*S+s][h*64+d] ----
    const float inv0 = 1.0f / lrun[0];
    const float inv1 = 1.0f / lrun[1];
    const int b = bh >> 4, h = bh & 15;
    const int r0 = q0 + wid * 16 + (lane >> 2);
    const int nl = (lane & 3) << 1;
#pragma unroll
    for (int nt = 0; nt < 8; nt++) {
        int d = nt * 8 + nl;
        size_t i0 = (size_t)(b * SEQ + r0) * DMODEL + h * 64 + d;
        *(uint32_t*)&s_c16[i0] = pack2h(ctxa[nt][0] * inv0, ctxa[nt][1] * inv0);
        size_t i1 = (size_t)(b * SEQ + r0 + 8) * DMODEL + h * 64 + d;
        *(uint32_t*)&s_c16[i1] = pack2h(ctxa[nt][2] * inv1, ctxa[nt][3] * inv1);
    }
}

// ---------------------------------------------------------------------------
extern "C" void kernel_launch(void* const* d_in, const int* in_sizes, int n_in,
                              void* d_out, int out_size)
{
    (void)in_sizes; (void)n_in; (void)out_size;
    const float* q  = (const float*)d_in[0];
    const float* k  = (const float*)d_in[1];
    const float* v  = (const float*)d_in[2];
    const float* Wq = (const float*)d_in[3];
    const float* bq = (const float*)d_in[4];
    const float* Wk = (const float*)d_in[5];
    const float* bk = (const float*)d_in[6];
    const float* Wv = (const float*)d_in[7];
    const float* bv = (const float*)d_in[8];
    const float* Wo = (const float*)d_in[9];
    const float* bo = (const float*)d_in[10];
    float* out = (float*)d_out;

    __half *xq, *xk, *xv, *c16, *w, *aq, *ak, *avt;
    cudaGetSymbolAddress((void**)&xq, s_xq);
    cudaGetSymbolAddress((void**)&xk, s_xk);
    cudaGetSymbolAddress((void**)&xv, s_xv);
    cudaGetSymbolAddress((void**)&c16, s_c16);
    cudaGetSymbolAddress((void**)&w, s_w);
    cudaGetSymbolAddress((void**)&aq, a_q);
    cudaGetSymbolAddress((void**)&ak, a_k);
    cudaGetSymbolAddress((void**)&avt, a_vt);

    const int GSM = 3 * GSTG;   // 72KB
    cudaFuncSetAttribute((const void*)gemm_mma<0>, cudaFuncAttributeMaxDynamicSharedMemorySize, GSM);
    cudaFuncSetAttribute((const void*)gemm_mma<2>, cudaFuncAttributeMaxDynamicSharedMemorySize, GSM);
    cudaFuncSetAttribute((const void*)gemm_mma<3>, cudaFuncAttributeMaxDynamicSharedMemorySize, GSM);
    cudaFuncSetAttribute(attn_mma, cudaFuncAttributeMaxDynamicSharedMemorySize, 49152);

    const size_t WSZ = (size_t)DMODEL * DMODEL;
    const int NX4 = MROWS * DMODEL / 4;
    const int NW4 = DMODEL * DMODEL / 4;
    cvt_kernel<<<NX4 / 256, 256>>>(q, xq, NX4);
    cvt_kernel<<<NX4 / 256, 256>>>(k, xk, NX4);
    cvt_kernel<<<NX4 / 256, 256>>>(v, xv, NX4);
    cvt_kernel<<<NW4 / 256, 256>>>(Wq, w + 0 * WSZ, NW4);
    cvt_kernel<<<NW4 / 256, 256>>>(Wk, w + 1 * WSZ, NW4);
    cvt_kernel<<<NW4 / 256, 256>>>(Wv, w + 2 * WSZ, NW4);
    cvt_kernel<<<NW4 / 256, 256>>>(Wo, w + 3 * WSZ, NW4);

    dim3 gg(DMODEL / 128, MROWS / 256);  // (8, 16)
    gemm_mma<3><<<gg, 256, GSM>>>(xq, w + 0 * WSZ, bq, nullptr, aq);
    gemm_mma<3><<<gg, 256, GSM>>>(xk, w + 1 * WSZ, bk, nullptr, ak);
    gemm_mma<2><<<gg, 256, GSM>>>(xv, w + 2 * WSZ, bv, nullptr, avt);

    attn_mma<<<dim3(BHN, SEQ / 128), 256, 49152>>>();

    gemm_mma<0><<<gg, 256, GSM>>>(c16, w + 3 * WSZ, bo, out, nullptr);
}